// round 9
// baseline (speedup 1.0000x reference)
#include <cuda_runtime.h>
#include <cuda_fp16.h>
#include <math.h>
#include <stdint.h>

#define N_NODES 50000
#define N_EDGES 800000
#define E_TOT   (N_EDGES + N_NODES)
#define FDIM    512
#define HEADS   8
#define HID     64
#define NEG_SLOPE 0.2f

// ---------------- scratch (device globals; no allocs allowed) ----------------
__device__ float  g_hA[(size_t)N_NODES * FDIM];
__device__ __half g_Ahi[(size_t)N_NODES * FDIM];
__device__ __half g_Alo[(size_t)N_NODES * FDIM];
__device__ __half g_Wthi[FDIM * FDIM];
__device__ __half g_Wtlo[FDIM * FDIM];
__device__ float  g_asrc[N_NODES * HEADS];
__device__ float  g_adst[N_NODES * HEADS];
__device__ int    g_deg[N_NODES];
__device__ int    g_rowptr[N_NODES + 1];
__device__ int    g_rowcur[N_NODES];
__device__ int    g_srclist[E_TOT];

// ============================ helpers ============================
__device__ __forceinline__ uint32_t smem_u32(const void* p) {
    uint32_t a;
    asm("{ .reg .u64 t; cvta.to.shared.u64 t, %1; cvt.u32.u64 %0, t; }" : "=r"(a) : "l"(p));
    return a;
}
__device__ __forceinline__ void mma_f16(float* d, const uint32_t* a, const uint32_t* b) {
    asm volatile(
        "mma.sync.aligned.m16n8k16.row.col.f32.f16.f16.f32 "
        "{%0,%1,%2,%3}, {%4,%5,%6,%7}, {%8,%9}, {%0,%1,%2,%3};"
        : "+f"(d[0]), "+f"(d[1]), "+f"(d[2]), "+f"(d[3])
        : "r"(a[0]), "r"(a[1]), "r"(a[2]), "r"(a[3]), "r"(b[0]), "r"(b[1]));
}
__device__ __forceinline__ void cp_async16(uint32_t saddr, const void* gaddr, int src_bytes) {
    asm volatile("cp.async.cg.shared.global [%0], [%1], 16, %2;"
                 :: "r"(saddr), "l"(gaddr), "r"(src_bytes));
}
#define CP_COMMIT() asm volatile("cp.async.commit_group;" ::: "memory")
#define CP_WAIT(n)  asm volatile("cp.async.wait_group %0;" :: "n"(n) : "memory")
#define LDU32(p) (*(const uint32_t*)(p))

// ============================ CSR build ============================
__global__ void zero_deg_kernel() {
    int i = blockIdx.x * blockDim.x + threadIdx.x;
    if (i < N_NODES) g_deg[i] = 0;
}
__global__ void count_kernel(const int* __restrict__ ei) {
    int idx = blockIdx.x * blockDim.x + threadIdx.x;
    if (idx >= E_TOT) return;
    int dst = (idx < N_EDGES) ? ei[N_EDGES + idx] : (idx - N_EDGES);
    atomicAdd(&g_deg[dst], 1);
}
__global__ void scan_kernel() {
    __shared__ int sums[1024];
    const int per = (N_NODES + 1023) / 1024;
    int t  = threadIdx.x;
    int lo = t * per;
    int hi = min(lo + per, N_NODES);
    int s = 0;
    for (int i = lo; i < hi; i++) s += g_deg[i];
    sums[t] = s;
    __syncthreads();
    if (t == 0) {
        int run = 0;
        for (int i = 0; i < 1024; i++) { int v = sums[i]; sums[i] = run; run += v; }
        g_rowptr[N_NODES] = run;
    }
    __syncthreads();
    int run = sums[t];
    for (int i = lo; i < hi; i++) {
        g_rowptr[i] = run;
        g_rowcur[i] = run;
        run += g_deg[i];
    }
}
__global__ void fill_kernel(const int* __restrict__ ei) {
    int idx = blockIdx.x * blockDim.x + threadIdx.x;
    if (idx >= E_TOT) return;
    int src, dst;
    if (idx < N_EDGES) { src = ei[idx]; dst = ei[N_EDGES + idx]; }
    else               { src = dst = idx - N_EDGES; }
    int pos = atomicAdd(&g_rowcur[dst], 1);
    g_srclist[pos] = src;
}

// ============================ fp16 hi/lo conversions ============================
#define KP0 128
__global__ void convert_x_kernel(const float* __restrict__ x) {
    int idx = blockIdx.x * blockDim.x + threadIdx.x;
    if (idx >= N_NODES * KP0) return;
    int n = idx >> 7, k = idx & (KP0 - 1);
    float v = (k < 69) ? x[n * 69 + k] : 0.f;
    __half h = __float2half_rn(v);
    g_Ahi[idx] = h;
    g_Alo[idx] = __float2half_rn(v - __half2float(h));
}
__global__ void convert_w_kernel(const float* __restrict__ W, int K, int Kp,
                                 __half* __restrict__ dhi, __half* __restrict__ dlo) {
    int idx = blockIdx.x * blockDim.x + threadIdx.x;
    if (idx >= FDIM * Kp) return;
    int n = idx / Kp, k = idx % Kp;
    float v = (k < K) ? W[(size_t)k * FDIM + n] : 0.f;
    __half h = __float2half_rn(v);
    dhi[idx] = h;
    dlo[idx] = __float2half_rn(v - __half2float(h));
}

// ============================ fp16 3-term warp-MMA GEMM + fused alpha ============
#define BM 128
#define BN 128
#define BK 64
#define TSTRIDE 72
#define TILE_HALFS (128 * TSTRIDE)
#define BUF_HALFS (4 * TILE_HALFS)
#define SMEM_GEMM (2 * BUF_HALFS * 2 + 128 * 4 * 4)

__global__ __launch_bounds__(256, 1) void mma_gemm_kernel(
    const __half* __restrict__ Ahi, const __half* __restrict__ Alo,
    const __half* __restrict__ Bhi, const __half* __restrict__ Blo,
    float* __restrict__ C, const float* __restrict__ aSrc, const float* __restrict__ aDst,
    int nrows, int Kp)
{
    extern __shared__ __half smh[];
    float* salpha = (float*)(smh + 2 * BUF_HALFS);   // [128][2 heads][2 (src,dst)]

    const int tid  = threadIdx.x;
    const int wid  = tid >> 5;
    const int lane = tid & 31;
    const int gid  = lane >> 2;
    const int tig  = lane & 3;
    const int warp_m = wid >> 2;
    const int warp_n = wid & 3;
    const int rowBase = blockIdx.y * BM;
    const int nBase   = blockIdx.x * BN;

    const int nch = Kp / BK;

    float acc[4][4][4];
#pragma unroll
    for (int i = 0; i < 4; i++)
#pragma unroll
        for (int j = 0; j < 4; j++)
#pragma unroll
            for (int q = 0; q < 4; q++) acc[i][j][q] = 0.f;

    const int lrow = tid >> 1, lseg = tid & 1;
    const int arow = rowBase + lrow;
    const int aok  = (arow < nrows) ? 16 : 0;
    const __half* gAhi = Ahi + (size_t)(aok ? arow : 0) * Kp + lseg * 32;
    const __half* gAlo = Alo + (size_t)(aok ? arow : 0) * Kp + lseg * 32;
    const __half* gBhi = Bhi + (size_t)(nBase + lrow) * Kp + lseg * 32;
    const __half* gBlo = Blo + (size_t)(nBase + lrow) * Kp + lseg * 32;
    const uint32_t sdst = smem_u32(smh) + (lrow * TSTRIDE + lseg * 32) * 2;

    auto loadChunk = [&](int ic, int buf) {
        const int k0 = ic * BK;
        const uint32_t b = sdst + buf * (BUF_HALFS * 2);
#pragma unroll
        for (int j = 0; j < 4; j++)
            cp_async16(b + j * 16, gAhi + k0 + j * 8, aok);
#pragma unroll
        for (int j = 0; j < 4; j++)
            cp_async16(b + TILE_HALFS * 2 + j * 16, gAlo + k0 + j * 8, aok);
#pragma unroll
        for (int j = 0; j < 4; j++)
            cp_async16(b + TILE_HALFS * 4 + j * 16, gBhi + k0 + j * 8, 16);
#pragma unroll
        for (int j = 0; j < 4; j++)
            cp_async16(b + TILE_HALFS * 6 + j * 16, gBlo + k0 + j * 8, 16);
        CP_COMMIT();
    };

    loadChunk(0, 0);
    if (tid < 128) {
        salpha[tid * 4 + 0] = 0.f; salpha[tid * 4 + 1] = 0.f;
        salpha[tid * 4 + 2] = 0.f; salpha[tid * 4 + 3] = 0.f;
    }

    for (int ic = 0; ic < nch; ic++) {
        if (ic + 1 < nch) { loadChunk(ic + 1, (ic + 1) & 1); CP_WAIT(1); }
        else              { CP_WAIT(0); }
        __syncthreads();

        const __half* asH = smh + (ic & 1) * BUF_HALFS;
        const __half* asL = asH + TILE_HALFS;
        const __half* bsH = asH + 2 * TILE_HALFS;
        const __half* bsL = asH + 3 * TILE_HALFS;
        const int arow0 = warp_m * 64 + gid;
        const int bcol0 = warp_n * 32 + gid;

#pragma unroll
        for (int kk = 0; kk < BK; kk += 16) {
            uint32_t ahi[4][4], alo[4][4], bhi[4][2], blo[4][2];
#pragma unroll
            for (int nt = 0; nt < 4; nt++) {
                const __half* ph = bsH + (bcol0 + nt * 8) * TSTRIDE + kk + tig * 2;
                const __half* pl = bsL + (bcol0 + nt * 8) * TSTRIDE + kk + tig * 2;
                bhi[nt][0] = LDU32(ph);     bhi[nt][1] = LDU32(ph + 8);
                blo[nt][0] = LDU32(pl);     blo[nt][1] = LDU32(pl + 8);
            }
#pragma unroll
            for (int mt = 0; mt < 4; mt++) {
                int r0 = arow0 + mt * 16;
                const __half* ph = asH + r0 * TSTRIDE + kk + tig * 2;
                const __half* pl = asL + r0 * TSTRIDE + kk + tig * 2;
                ahi[mt][0] = LDU32(ph);                  ahi[mt][1] = LDU32(ph + 8 * TSTRIDE);
                ahi[mt][2] = LDU32(ph + 8);              ahi[mt][3] = LDU32(ph + 8 * TSTRIDE + 8);
                alo[mt][0] = LDU32(pl);                  alo[mt][1] = LDU32(pl + 8 * TSTRIDE);
                alo[mt][2] = LDU32(pl + 8);              alo[mt][3] = LDU32(pl + 8 * TSTRIDE + 8);
            }
#pragma unroll
            for (int mt = 0; mt < 4; mt++)
#pragma unroll
                for (int nt = 0; nt < 4; nt++)
                    mma_f16(acc[mt][nt], ahi[mt], bhi[nt]);
#pragma unroll
            for (int mt = 0; mt < 4; mt++)
#pragma unroll
                for (int nt = 0; nt < 4; nt++)
                    mma_f16(acc[mt][nt], ahi[mt], blo[nt]);
#pragma unroll
            for (int mt = 0; mt < 4; mt++)
#pragma unroll
                for (int nt = 0; nt < 4; nt++)
                    mma_f16(acc[mt][nt], alo[mt], bhi[nt]);
        }
        __syncthreads();
    }

    // ---- epilogue: store C + fused alpha partial dots ----
    const int hl = warp_n >> 1;
    float s1[4][2], s2[4][2];
#pragma unroll
    for (int mt = 0; mt < 4; mt++) { s1[mt][0]=0.f; s1[mt][1]=0.f; s2[mt][0]=0.f; s2[mt][1]=0.f; }

#pragma unroll
    for (int mt = 0; mt < 4; mt++) {
        int r0 = rowBase + warp_m * 64 + mt * 16 + gid;
        int r1 = r0 + 8;
#pragma unroll
        for (int nt = 0; nt < 4; nt++) {
            int col = nBase + warp_n * 32 + nt * 8 + 2 * tig;
            float2 aS2 = *(const float2*)(aSrc + col);
            float2 aD2 = *(const float2*)(aDst + col);
            if (r0 < nrows)
                *(float2*)(C + (size_t)r0 * FDIM + col) =
                    make_float2(acc[mt][nt][0], acc[mt][nt][1]);
            if (r1 < nrows)
                *(float2*)(C + (size_t)r1 * FDIM + col) =
                    make_float2(acc[mt][nt][2], acc[mt][nt][3]);
            s1[mt][0] += acc[mt][nt][0] * aS2.x + acc[mt][nt][1] * aS2.y;
            s2[mt][0] += acc[mt][nt][0] * aD2.x + acc[mt][nt][1] * aD2.y;
            s1[mt][1] += acc[mt][nt][2] * aS2.x + acc[mt][nt][3] * aS2.y;
            s2[mt][1] += acc[mt][nt][2] * aD2.x + acc[mt][nt][3] * aD2.y;
        }
    }
#pragma unroll
    for (int mt = 0; mt < 4; mt++)
#pragma unroll
        for (int j = 0; j < 2; j++) {
            s1[mt][j] += __shfl_down_sync(0xffffffffu, s1[mt][j], 2, 4);
            s1[mt][j] += __shfl_down_sync(0xffffffffu, s1[mt][j], 1, 4);
            s2[mt][j] += __shfl_down_sync(0xffffffffu, s2[mt][j], 2, 4);
            s2[mt][j] += __shfl_down_sync(0xffffffffu, s2[mt][j], 1, 4);
        }
    if (tig == 0) {
#pragma unroll
        for (int mt = 0; mt < 4; mt++) {
            int lr0 = warp_m * 64 + mt * 16 + gid;
            atomicAdd(&salpha[lr0 * 4 + hl * 2 + 0], s1[mt][0]);
            atomicAdd(&salpha[lr0 * 4 + hl * 2 + 1], s2[mt][0]);
            atomicAdd(&salpha[(lr0 + 8) * 4 + hl * 2 + 0], s1[mt][1]);
            atomicAdd(&salpha[(lr0 + 8) * 4 + hl * 2 + 1], s2[mt][1]);
        }
    }
    __syncthreads();
    if (tid < 128) {
        int grow = rowBase + tid;
        if (grow < nrows) {
            int hbase = (nBase >> 6);
            g_asrc[grow * HEADS + hbase]     = salpha[tid * 4 + 0];
            g_adst[grow * HEADS + hbase]     = salpha[tid * 4 + 1];
            g_asrc[grow * HEADS + hbase + 1] = salpha[tid * 4 + 2];
            g_adst[grow * HEADS + hbase + 1] = salpha[tid * 4 + 3];
        }
    }
}

// ---------------- warp-per-node online-softmax aggregation ----------------
// One warp per dst node; lane t owns channels [16t, 16t+16) (head = t>>2).
// mode 0: relu + write fp16 hi/lo. mode 1: fused prediction head -> out.
#define AGG_WARPS 8
__global__ __launch_bounds__(32 * AGG_WARPS) void aggregate_kernel(
    const float* __restrict__ h, const float* __restrict__ bias,
    __half* __restrict__ outHi, __half* __restrict__ outLo,
    const float* __restrict__ predW, const float* __restrict__ predb,
    float* __restrict__ out, int mode)
{
    const int d = blockIdx.x * AGG_WARPS + (threadIdx.x >> 5);
    if (d >= N_NODES) return;
    const int lane = threadIdx.x & 31;
    const int head = lane >> 2;
    const int c0 = lane * 16;

    const int start = g_rowptr[d], end = g_rowptr[d + 1];
    const float adst_v = g_adst[d * HEADS + head];

    float m = -INFINITY, denom = 0.f;
    float4 a0 = make_float4(0.f,0.f,0.f,0.f), a1 = a0, a2 = a0, a3 = a0;

#pragma unroll 2
    for (int i = start; i < end; i++) {
        int s = g_srclist[i];                       // warp-broadcast load
        float e = g_asrc[s * HEADS + head] + adst_v;
        e = (e > 0.f) ? e : NEG_SLOPE * e;
        if (e > m) {
            float sc = __expf(m - e);
            m = e;
            denom *= sc;
            a0.x*=sc; a0.y*=sc; a0.z*=sc; a0.w*=sc;
            a1.x*=sc; a1.y*=sc; a1.z*=sc; a1.w*=sc;
            a2.x*=sc; a2.y*=sc; a2.z*=sc; a2.w*=sc;
            a3.x*=sc; a3.y*=sc; a3.z*=sc; a3.w*=sc;
        }
        float w = __expf(e - m);
        denom += w;
        const float4* hv = (const float4*)(h + (size_t)s * FDIM + c0);
        float4 v0 = hv[0], v1 = hv[1], v2 = hv[2], v3 = hv[3];
        a0.x += w*v0.x; a0.y += w*v0.y; a0.z += w*v0.z; a0.w += w*v0.w;
        a1.x += w*v1.x; a1.y += w*v1.y; a1.z += w*v1.z; a1.w += w*v1.w;
        a2.x += w*v2.x; a2.y += w*v2.y; a2.z += w*v2.z; a2.w += w*v2.w;
        a3.x += w*v3.x; a3.y += w*v3.y; a3.z += w*v3.z; a3.w += w*v3.w;
    }

    const float inv = 1.f / (denom + 1e-16f);
    const float4* b4 = (const float4*)(bias + c0);
    float o[16];
    float4 bb0 = b4[0], bb1 = b4[1], bb2 = b4[2], bb3 = b4[3];
    o[0]=a0.x*inv+bb0.x;  o[1]=a0.y*inv+bb0.y;  o[2]=a0.z*inv+bb0.z;  o[3]=a0.w*inv+bb0.w;
    o[4]=a1.x*inv+bb1.x;  o[5]=a1.y*inv+bb1.y;  o[6]=a1.z*inv+bb1.z;  o[7]=a1.w*inv+bb1.w;
    o[8]=a2.x*inv+bb2.x;  o[9]=a2.y*inv+bb2.y;  o[10]=a2.z*inv+bb2.z; o[11]=a2.w*inv+bb2.w;
    o[12]=a3.x*inv+bb3.x; o[13]=a3.y*inv+bb3.y; o[14]=a3.z*inv+bb3.z; o[15]=a3.w*inv+bb3.w;

    if (mode == 0) {
        __half2 hi[8], lo[8];
#pragma unroll
        for (int j = 0; j < 16; j++) o[j] = fmaxf(o[j], 0.f);
#pragma unroll
        for (int j = 0; j < 8; j++) {
            __half hx = __float2half_rn(o[2*j]), hy = __float2half_rn(o[2*j+1]);
            hi[j] = __halves2half2(hx, hy);
            lo[j] = __halves2half2(__float2half_rn(o[2*j]   - __half2float(hx)),
                                   __float2half_rn(o[2*j+1] - __half2float(hy)));
        }
        size_t idx = (size_t)d * FDIM + c0;
        uint4* ph = (uint4*)(outHi + idx);
        uint4* pl = (uint4*)(outLo + idx);
        ph[0] = *(uint4*)&hi[0]; ph[1] = *(uint4*)&hi[4];
        pl[0] = *(uint4*)&lo[0]; pl[1] = *(uint4*)&lo[4];
    } else {
        float p0 = 0.f, p1 = 0.f, p2 = 0.f;
#pragma unroll
        for (int j = 0; j < 16; j++) {
            int c = c0 + j;
            p0 += o[j] * predW[c * 3 + 0];
            p1 += o[j] * predW[c * 3 + 1];
            p2 += o[j] * predW[c * 3 + 2];
        }
#pragma unroll
        for (int off = 16; off > 0; off >>= 1) {
            p0 += __shfl_down_sync(0xffffffffu, p0, off);
            p1 += __shfl_down_sync(0xffffffffu, p1, off);
            p2 += __shfl_down_sync(0xffffffffu, p2, off);
        }
        if (lane == 0) {
            out[d * 3 + 0] = p0 + predb[0];
            out[d * 3 + 1] = p1 + predb[1];
            out[d * 3 + 2] = p2 + predb[2];
        }
    }
}

// ---------------- launch ----------------
extern "C" void kernel_launch(void* const* d_in, const int* in_sizes, int n_in,
                              void* d_out, int out_size)
{
    const float* x     = (const float*)d_in[0];   // [N,69]
    const int*   ei    = (const int*)  d_in[1];   // [2,E]
    const float* W[3]    = {(const float*)d_in[3],  (const float*)d_in[7],  (const float*)d_in[11]};
    const float* aS[3]   = {(const float*)d_in[4],  (const float*)d_in[8],  (const float*)d_in[12]};
    const float* aD[3]   = {(const float*)d_in[5],  (const float*)d_in[9],  (const float*)d_in[13]};
    const float* bb[3]   = {(const float*)d_in[6],  (const float*)d_in[10], (const float*)d_in[14]};
    const float* predW = (const float*)d_in[15];
    const float* predb = (const float*)d_in[16];
    float* out = (float*)d_out;

    float*  hA;  cudaGetSymbolAddress((void**)&hA,  g_hA);
    __half* Ahi; cudaGetSymbolAddress((void**)&Ahi, g_Ahi);
    __half* Alo; cudaGetSymbolAddress((void**)&Alo, g_Alo);
    __half* Whi; cudaGetSymbolAddress((void**)&Whi, g_Wthi);
    __half* Wlo; cudaGetSymbolAddress((void**)&Wlo, g_Wtlo);

    cudaFuncSetAttribute(mma_gemm_kernel,
                         cudaFuncAttributeMaxDynamicSharedMemorySize, SMEM_GEMM);

    // CSR build (same edges every layer)
    zero_deg_kernel<<<(N_NODES + 255) / 256, 256>>>();
    count_kernel<<<(E_TOT + 255) / 256, 256>>>(ei);
    scan_kernel<<<1, 1024>>>();
    fill_kernel<<<(E_TOT + 255) / 256, 256>>>(ei);

    convert_x_kernel<<<(N_NODES * KP0 + 255) / 256, 256>>>(x);

    const int K_in[3] = {69, FDIM, FDIM};
    for (int l = 0; l < 3; l++) {
        int Kp = (l == 0) ? KP0 : FDIM;
        convert_w_kernel<<<(FDIM * Kp + 255) / 256, 256>>>(W[l], K_in[l], Kp, Whi, Wlo);
        dim3 grid(FDIM / BN, (N_NODES + BM - 1) / BM);
        mma_gemm_kernel<<<grid, 256, SMEM_GEMM>>>(Ahi, Alo, Whi, Wlo, hA,
                                                  aS[l], aD[l], N_NODES, Kp);
        aggregate_kernel<<<(N_NODES + AGG_WARPS - 1) / AGG_WARPS, 32 * AGG_WARPS>>>(
            hA, bb[l], Ahi, Alo, predW, predb, out, (l == 2) ? 1 : 0);
    }
}

// round 10
// speedup vs baseline: 1.2228x; 1.2228x over previous
#include <cuda_runtime.h>
#include <cuda_fp16.h>
#include <math.h>
#include <stdint.h>

#define N_NODES 50000
#define N_EDGES 800000
#define E_TOT   (N_EDGES + N_NODES)
#define FDIM    512
#define HEADS   8
#define HID     64
#define NEG_SLOPE 0.2f

// ---------------- scratch (device globals; no allocs allowed) ----------------
__device__ float  g_hA[(size_t)N_NODES * FDIM];
__device__ __half g_Ahi[(size_t)N_NODES * FDIM];
__device__ __half g_Alo[(size_t)N_NODES * FDIM];
__device__ __half g_Wthi[FDIM * FDIM];
__device__ __half g_Wtlo[FDIM * FDIM];
__device__ float  g_asrc[N_NODES * HEADS];
__device__ float  g_adst[N_NODES * HEADS];
__device__ int    g_deg[N_NODES];
__device__ int    g_rowptr[N_NODES + 1];
__device__ int    g_rowcur[N_NODES];
__device__ int    g_srclist[E_TOT];

// ============================ helpers ============================
__device__ __forceinline__ uint32_t smem_u32(const void* p) {
    uint32_t a;
    asm("{ .reg .u64 t; cvta.to.shared.u64 t, %1; cvt.u32.u64 %0, t; }" : "=r"(a) : "l"(p));
    return a;
}
__device__ __forceinline__ void mma_f16(float* d, const uint32_t* a, const uint32_t* b) {
    asm volatile(
        "mma.sync.aligned.m16n8k16.row.col.f32.f16.f16.f32 "
        "{%0,%1,%2,%3}, {%4,%5,%6,%7}, {%8,%9}, {%0,%1,%2,%3};"
        : "+f"(d[0]), "+f"(d[1]), "+f"(d[2]), "+f"(d[3])
        : "r"(a[0]), "r"(a[1]), "r"(a[2]), "r"(a[3]), "r"(b[0]), "r"(b[1]));
}
__device__ __forceinline__ void ldsm_x4(uint32_t& r0, uint32_t& r1, uint32_t& r2,
                                        uint32_t& r3, uint32_t addr) {
    asm volatile("ldmatrix.sync.aligned.m8n8.x4.shared.b16 {%0,%1,%2,%3}, [%4];"
                 : "=r"(r0), "=r"(r1), "=r"(r2), "=r"(r3) : "r"(addr));
}
__device__ __forceinline__ void cp_async16(uint32_t saddr, const void* gaddr, int src_bytes) {
    asm volatile("cp.async.cg.shared.global [%0], [%1], 16, %2;"
                 :: "r"(saddr), "l"(gaddr), "r"(src_bytes));
}
#define CP_COMMIT() asm volatile("cp.async.commit_group;" ::: "memory")
#define CP_WAIT(n)  asm volatile("cp.async.wait_group %0;" :: "n"(n) : "memory")

// ============================ CSR build ============================
__global__ void zero_deg_kernel() {
    int i = blockIdx.x * blockDim.x + threadIdx.x;
    if (i < N_NODES) g_deg[i] = 0;
}
__global__ void count_kernel(const int* __restrict__ ei) {
    int idx = blockIdx.x * blockDim.x + threadIdx.x;
    if (idx >= E_TOT) return;
    int dst = (idx < N_EDGES) ? ei[N_EDGES + idx] : (idx - N_EDGES);
    atomicAdd(&g_deg[dst], 1);
}
__global__ void scan_kernel() {
    __shared__ int sums[1024];
    const int per = (N_NODES + 1023) / 1024;
    int t  = threadIdx.x;
    int lo = t * per;
    int hi = min(lo + per, N_NODES);
    int s = 0;
    for (int i = lo; i < hi; i++) s += g_deg[i];
    sums[t] = s;
    __syncthreads();
    if (t == 0) {
        int run = 0;
        for (int i = 0; i < 1024; i++) { int v = sums[i]; sums[i] = run; run += v; }
        g_rowptr[N_NODES] = run;
    }
    __syncthreads();
    int run = sums[t];
    for (int i = lo; i < hi; i++) {
        g_rowptr[i] = run;
        g_rowcur[i] = run;
        run += g_deg[i];
    }
}
__global__ void fill_kernel(const int* __restrict__ ei) {
    int idx = blockIdx.x * blockDim.x + threadIdx.x;
    if (idx >= E_TOT) return;
    int src, dst;
    if (idx < N_EDGES) { src = ei[idx]; dst = ei[N_EDGES + idx]; }
    else               { src = dst = idx - N_EDGES; }
    int pos = atomicAdd(&g_rowcur[dst], 1);
    g_srclist[pos] = src;
}

// ============================ fp16 hi/lo conversions ============================
#define KP0 128
__global__ void convert_x_kernel(const float* __restrict__ x) {
    int idx = blockIdx.x * blockDim.x + threadIdx.x;
    if (idx >= N_NODES * KP0) return;
    int n = idx >> 7, k = idx & (KP0 - 1);
    float v = (k < 69) ? x[n * 69 + k] : 0.f;
    __half h = __float2half_rn(v);
    g_Ahi[idx] = h;
    g_Alo[idx] = __float2half_rn(v - __half2float(h));
}
__global__ void convert_w_kernel(const float* __restrict__ W, int K, int Kp,
                                 __half* __restrict__ dhi, __half* __restrict__ dlo) {
    int idx = blockIdx.x * blockDim.x + threadIdx.x;
    if (idx >= FDIM * Kp) return;
    int n = idx / Kp, k = idx % Kp;
    float v = (k < K) ? W[(size_t)k * FDIM + n] : 0.f;
    __half h = __float2half_rn(v);
    dhi[idx] = h;
    dlo[idx] = __float2half_rn(v - __half2float(h));
}

// ============================ fp16 3-term warp-MMA GEMM + fused alpha ============
#define BM 128
#define BN 128
#define BK 64
#define TSTRIDE 72
#define TILE_HALFS (128 * TSTRIDE)
#define BUF_HALFS (4 * TILE_HALFS)
#define SMEM_GEMM (2 * BUF_HALFS * 2 + 128 * 4 * 4)

__global__ __launch_bounds__(256, 1) void mma_gemm_kernel(
    const __half* __restrict__ Ahi, const __half* __restrict__ Alo,
    const __half* __restrict__ Bhi, const __half* __restrict__ Blo,
    float* __restrict__ C, const float* __restrict__ aSrc, const float* __restrict__ aDst,
    int nrows, int Kp)
{
    extern __shared__ __half smh[];
    float* salpha = (float*)(smh + 2 * BUF_HALFS);   // [128][2 heads][2 (src,dst)]

    const int tid  = threadIdx.x;
    const int wid  = tid >> 5;
    const int lane = tid & 31;
    const int gid  = lane >> 2;
    const int tig  = lane & 3;
    const int warp_m = wid >> 2;
    const int warp_n = wid & 3;
    const int rowBase = blockIdx.y * BM;
    const int nBase   = blockIdx.x * BN;

    const int nch = Kp / BK;

    float acc[4][4][4];
#pragma unroll
    for (int i = 0; i < 4; i++)
#pragma unroll
        for (int j = 0; j < 4; j++)
#pragma unroll
            for (int q = 0; q < 4; q++) acc[i][j][q] = 0.f;

    const int lrow = tid >> 1, lseg = tid & 1;
    const int arow = rowBase + lrow;
    const int aok  = (arow < nrows) ? 16 : 0;
    const __half* gAhi = Ahi + (size_t)(aok ? arow : 0) * Kp + lseg * 32;
    const __half* gAlo = Alo + (size_t)(aok ? arow : 0) * Kp + lseg * 32;
    const __half* gBhi = Bhi + (size_t)(nBase + lrow) * Kp + lseg * 32;
    const __half* gBlo = Blo + (size_t)(nBase + lrow) * Kp + lseg * 32;
    const uint32_t sbase = smem_u32(smh);
    const uint32_t sdst = sbase + (lrow * TSTRIDE + lseg * 32) * 2;

    // per-lane ldmatrix address components (bytes)
    const int aoff = ((warp_m * 64 + (lane & 15)) * TSTRIDE + (lane >> 4) * 8) * 2;
    const int boff = ((warp_n * 32 + (lane >> 4) * 8 + (lane & 7)) * TSTRIDE
                      + ((lane >> 3) & 1) * 8) * 2;

    auto loadChunk = [&](int ic, int buf) {
        const int k0 = ic * BK;
        const uint32_t b = sdst + buf * (BUF_HALFS * 2);
#pragma unroll
        for (int j = 0; j < 4; j++)
            cp_async16(b + j * 16, gAhi + k0 + j * 8, aok);
#pragma unroll
        for (int j = 0; j < 4; j++)
            cp_async16(b + TILE_HALFS * 2 + j * 16, gAlo + k0 + j * 8, aok);
#pragma unroll
        for (int j = 0; j < 4; j++)
            cp_async16(b + TILE_HALFS * 4 + j * 16, gBhi + k0 + j * 8, 16);
#pragma unroll
        for (int j = 0; j < 4; j++)
            cp_async16(b + TILE_HALFS * 6 + j * 16, gBlo + k0 + j * 8, 16);
        CP_COMMIT();
    };

    loadChunk(0, 0);
    if (tid < 128) {
        salpha[tid * 4 + 0] = 0.f; salpha[tid * 4 + 1] = 0.f;
        salpha[tid * 4 + 2] = 0.f; salpha[tid * 4 + 3] = 0.f;
    }

    for (int ic = 0; ic < nch; ic++) {
        if (ic + 1 < nch) { loadChunk(ic + 1, (ic + 1) & 1); CP_WAIT(1); }
        else              { CP_WAIT(0); }
        __syncthreads();

        const uint32_t asHb = sbase + (ic & 1) * (BUF_HALFS * 2);
        const uint32_t asLb = asHb + TILE_HALFS * 2;
        const uint32_t bsHb = asHb + 2 * TILE_HALFS * 2;
        const uint32_t bsLb = asHb + 3 * TILE_HALFS * 2;

#pragma unroll
        for (int kk = 0; kk < BK; kk += 16) {
            uint32_t ahi[4][4], alo[4][4], bhi[4][2], blo[4][2];
            // B frags: one ldmatrix.x4 covers two n-tiles (hi and lo separately)
            ldsm_x4(bhi[0][0], bhi[0][1], bhi[1][0], bhi[1][1], bsHb + boff + kk * 2);
            ldsm_x4(bhi[2][0], bhi[2][1], bhi[3][0], bhi[3][1],
                    bsHb + boff + (16 * TSTRIDE + kk) * 2);
            ldsm_x4(blo[0][0], blo[0][1], blo[1][0], blo[1][1], bsLb + boff + kk * 2);
            ldsm_x4(blo[2][0], blo[2][1], blo[3][0], blo[3][1],
                    bsLb + boff + (16 * TSTRIDE + kk) * 2);
            // A frags: one ldmatrix.x4 per mt
#pragma unroll
            for (int mt = 0; mt < 4; mt++) {
                ldsm_x4(ahi[mt][0], ahi[mt][1], ahi[mt][2], ahi[mt][3],
                        asHb + aoff + (mt * 16 * TSTRIDE + kk) * 2);
                ldsm_x4(alo[mt][0], alo[mt][1], alo[mt][2], alo[mt][3],
                        asLb + aoff + (mt * 16 * TSTRIDE + kk) * 2);
            }
#pragma unroll
            for (int mt = 0; mt < 4; mt++)
#pragma unroll
                for (int nt = 0; nt < 4; nt++)
                    mma_f16(acc[mt][nt], ahi[mt], bhi[nt]);
#pragma unroll
            for (int mt = 0; mt < 4; mt++)
#pragma unroll
                for (int nt = 0; nt < 4; nt++)
                    mma_f16(acc[mt][nt], ahi[mt], blo[nt]);
#pragma unroll
            for (int mt = 0; mt < 4; mt++)
#pragma unroll
                for (int nt = 0; nt < 4; nt++)
                    mma_f16(acc[mt][nt], alo[mt], bhi[nt]);
        }
        __syncthreads();
    }

    // ---- epilogue: store C + fused alpha partial dots ----
    const int hl = warp_n >> 1;
    float s1[4][2], s2[4][2];
#pragma unroll
    for (int mt = 0; mt < 4; mt++) { s1[mt][0]=0.f; s1[mt][1]=0.f; s2[mt][0]=0.f; s2[mt][1]=0.f; }

#pragma unroll
    for (int mt = 0; mt < 4; mt++) {
        int r0 = rowBase + warp_m * 64 + mt * 16 + gid;
        int r1 = r0 + 8;
#pragma unroll
        for (int nt = 0; nt < 4; nt++) {
            int col = nBase + warp_n * 32 + nt * 8 + 2 * tig;
            float2 aS2 = *(const float2*)(aSrc + col);
            float2 aD2 = *(const float2*)(aDst + col);
            if (r0 < nrows)
                *(float2*)(C + (size_t)r0 * FDIM + col) =
                    make_float2(acc[mt][nt][0], acc[mt][nt][1]);
            if (r1 < nrows)
                *(float2*)(C + (size_t)r1 * FDIM + col) =
                    make_float2(acc[mt][nt][2], acc[mt][nt][3]);
            s1[mt][0] += acc[mt][nt][0] * aS2.x + acc[mt][nt][1] * aS2.y;
            s2[mt][0] += acc[mt][nt][0] * aD2.x + acc[mt][nt][1] * aD2.y;
            s1[mt][1] += acc[mt][nt][2] * aS2.x + acc[mt][nt][3] * aS2.y;
            s2[mt][1] += acc[mt][nt][2] * aD2.x + acc[mt][nt][3] * aD2.y;
        }
    }
#pragma unroll
    for (int mt = 0; mt < 4; mt++)
#pragma unroll
        for (int j = 0; j < 2; j++) {
            s1[mt][j] += __shfl_down_sync(0xffffffffu, s1[mt][j], 2, 4);
            s1[mt][j] += __shfl_down_sync(0xffffffffu, s1[mt][j], 1, 4);
            s2[mt][j] += __shfl_down_sync(0xffffffffu, s2[mt][j], 2, 4);
            s2[mt][j] += __shfl_down_sync(0xffffffffu, s2[mt][j], 1, 4);
        }
    if (tig == 0) {
#pragma unroll
        for (int mt = 0; mt < 4; mt++) {
            int lr0 = warp_m * 64 + mt * 16 + gid;
            atomicAdd(&salpha[lr0 * 4 + hl * 2 + 0], s1[mt][0]);
            atomicAdd(&salpha[lr0 * 4 + hl * 2 + 1], s2[mt][0]);
            atomicAdd(&salpha[(lr0 + 8) * 4 + hl * 2 + 0], s1[mt][1]);
            atomicAdd(&salpha[(lr0 + 8) * 4 + hl * 2 + 1], s2[mt][1]);
        }
    }
    __syncthreads();
    if (tid < 128) {
        int grow = rowBase + tid;
        if (grow < nrows) {
            int hbase = (nBase >> 6);
            g_asrc[grow * HEADS + hbase]     = salpha[tid * 4 + 0];
            g_adst[grow * HEADS + hbase]     = salpha[tid * 4 + 1];
            g_asrc[grow * HEADS + hbase + 1] = salpha[tid * 4 + 2];
            g_adst[grow * HEADS + hbase + 1] = salpha[tid * 4 + 3];
        }
    }
}

// ---------------- fused online-softmax aggregation (R8 core) ----------------
// mode 0: relu + write fp16 hi/lo (input of next GEMM)
// mode 1: fused prediction head -> out[d*3..]
#define AGG_CHUNK 256
__global__ __launch_bounds__(128) void aggregate_kernel(
    const float* __restrict__ h, const float* __restrict__ bias,
    __half* __restrict__ outHi, __half* __restrict__ outLo,
    const float* __restrict__ predW, const float* __restrict__ predb,
    float* __restrict__ out, int mode)
{
    int d = blockIdx.x;
    int t = threadIdx.x;            // 128 threads, 4 channels each
    int head = t >> 4;
    int start = g_rowptr[d], end = g_rowptr[d + 1];
    float adst_v = g_adst[d * HEADS + head];

    __shared__ int ssrc[AGG_CHUNK];
    __shared__ float spred[3];

    float m = -INFINITY, denom = 0.f;
    float4 acc = make_float4(0.f, 0.f, 0.f, 0.f);

    for (int base = start; base < end; base += AGG_CHUNK) {
        int cnt = min(AGG_CHUNK, end - base);
        __syncthreads();
        for (int i = t; i < cnt; i += 128) ssrc[i] = g_srclist[base + i];
        if (t < 3 && base == start) spred[t] = 0.f;
        __syncthreads();
#pragma unroll 4
        for (int i = 0; i < cnt; i++) {
            int s = ssrc[i];
            float e = g_asrc[s * HEADS + head] + adst_v;
            e = (e > 0.f) ? e : NEG_SLOPE * e;
            if (e > m) {
                float sc = __expf(m - e);
                m = e;
                denom *= sc;
                acc.x *= sc; acc.y *= sc; acc.z *= sc; acc.w *= sc;
            }
            float w = __expf(e - m);
            denom += w;
            float4 hv = *(const float4*)(h + (size_t)s * FDIM + t * 4);
            acc.x += w * hv.x; acc.y += w * hv.y;
            acc.z += w * hv.z; acc.w += w * hv.w;
        }
    }

    float inv = 1.f / (denom + 1e-16f);
    float4 b4 = *(const float4*)(bias + t * 4);
    float4 o;
    o.x = acc.x * inv + b4.x; o.y = acc.y * inv + b4.y;
    o.z = acc.z * inv + b4.z; o.w = acc.w * inv + b4.w;

    if (mode == 0) {
        o.x = fmaxf(o.x, 0.f); o.y = fmaxf(o.y, 0.f);
        o.z = fmaxf(o.z, 0.f); o.w = fmaxf(o.w, 0.f);
        size_t idx = (size_t)d * FDIM + t * 4;
        __half hx = __float2half_rn(o.x), hy = __float2half_rn(o.y);
        __half hz = __float2half_rn(o.z), hw = __float2half_rn(o.w);
        __half2* ph = (__half2*)(outHi + idx);
        ph[0] = __halves2half2(hx, hy);
        ph[1] = __halves2half2(hz, hw);
        __half2* pl = (__half2*)(outLo + idx);
        pl[0] = __halves2half2(__float2half_rn(o.x - __half2float(hx)),
                               __float2half_rn(o.y - __half2float(hy)));
        pl[1] = __halves2half2(__float2half_rn(o.z - __half2float(hz)),
                               __float2half_rn(o.w - __half2float(hw)));
    } else {
        int c0 = t * 4;
        float p0 = o.x * predW[(c0+0)*3+0] + o.y * predW[(c0+1)*3+0]
                 + o.z * predW[(c0+2)*3+0] + o.w * predW[(c0+3)*3+0];
        float p1 = o.x * predW[(c0+0)*3+1] + o.y * predW[(c0+1)*3+1]
                 + o.z * predW[(c0+2)*3+1] + o.w * predW[(c0+3)*3+1];
        float p2 = o.x * predW[(c0+0)*3+2] + o.y * predW[(c0+1)*3+2]
                 + o.z * predW[(c0+2)*3+2] + o.w * predW[(c0+3)*3+2];
#pragma unroll
        for (int off = 16; off > 0; off >>= 1) {
            p0 += __shfl_down_sync(0xffffffffu, p0, off);
            p1 += __shfl_down_sync(0xffffffffu, p1, off);
            p2 += __shfl_down_sync(0xffffffffu, p2, off);
        }
        if ((t & 31) == 0) {
            atomicAdd(&spred[0], p0);
            atomicAdd(&spred[1], p1);
            atomicAdd(&spred[2], p2);
        }
        __syncthreads();
        if (t < 3) out[d * 3 + t] = spred[t] + predb[t];
    }
}

// ---------------- launch ----------------
extern "C" void kernel_launch(void* const* d_in, const int* in_sizes, int n_in,
                              void* d_out, int out_size)
{
    const float* x     = (const float*)d_in[0];   // [N,69]
    const int*   ei    = (const int*)  d_in[1];   // [2,E]
    const float* W[3]    = {(const float*)d_in[3],  (const float*)d_in[7],  (const float*)d_in[11]};
    const float* aS[3]   = {(const float*)d_in[4],  (const float*)d_in[8],  (const float*)d_in[12]};
    const float* aD[3]   = {(const float*)d_in[5],  (const float*)d_in[9],  (const float*)d_in[13]};
    const float* bb[3]   = {(const float*)d_in[6],  (const float*)d_in[10], (const float*)d_in[14]};
    const float* predW = (const float*)d_in[15];
    const float* predb = (const float*)d_in[16];
    float* out = (float*)d_out;

    float*  hA;  cudaGetSymbolAddress((void**)&hA,  g_hA);
    __half* Ahi; cudaGetSymbolAddress((void**)&Ahi, g_Ahi);
    __half* Alo; cudaGetSymbolAddress((void**)&Alo, g_Alo);
    __half* Whi; cudaGetSymbolAddress((void**)&Whi, g_Wthi);
    __half* Wlo; cudaGetSymbolAddress((void**)&Wlo, g_Wtlo);

    cudaFuncSetAttribute(mma_gemm_kernel,
                         cudaFuncAttributeMaxDynamicSharedMemorySize, SMEM_GEMM);

    // CSR build (same edges every layer)
    zero_deg_kernel<<<(N_NODES + 255) / 256, 256>>>();
    count_kernel<<<(E_TOT + 255) / 256, 256>>>(ei);
    scan_kernel<<<1, 1024>>>();
    fill_kernel<<<(E_TOT + 255) / 256, 256>>>(ei);

    convert_x_kernel<<<(N_NODES * KP0 + 255) / 256, 256>>>(x);

    const int K_in[3] = {69, FDIM, FDIM};
    for (int l = 0; l < 3; l++) {
        int Kp = (l == 0) ? KP0 : FDIM;
        convert_w_kernel<<<(FDIM * Kp + 255) / 256, 256>>>(W[l], K_in[l], Kp, Whi, Wlo);
        dim3 grid(FDIM / BN, (N_NODES + BM - 1) / BM);
        mma_gemm_kernel<<<grid, 256, SMEM_GEMM>>>(Ahi, Alo, Whi, Wlo, hA,
                                                  aS[l], aD[l], N_NODES, Kp);
        aggregate_kernel<<<N_NODES, 128>>>(hA, bb[l], Ahi, Alo,
                                           predW, predb, out, (l == 2) ? 1 : 0);
    }
}